// round 16
// baseline (speedup 1.0000x reference)
#include <cuda_runtime.h>
#include <cuda_fp16.h>
#include <cstdint>

// TriPlane bilinear sampling, GB300 — round 16 (final, converged).
// Design (validated over R1-R15):
//  - transpose+convert planes [C,H,W] f32 -> [H,W,C] fp16, pre-scaled by 1/3
//    (channels contiguous -> coalesced texel gathers; fp16 halves L2 bytes)
//  - sampler: 16 lanes/point, LDG.64 = 2 lines/instr (measured optimum of the
//    L1 wavefront cost model), 12 loads issued upfront, half2 accumulation,
//    streaming f32 output stores.
// Sampler sits ~12% above the L1 service floor; all scheduling/occupancy/
// width levers measured neutral or negative.

#define NPTS   1048576
#define RES    256
#define FEAT   64
#define PLANE_ELEMS (RES * RES * FEAT)

__device__ __half g_tp16[3 * PLANE_ELEMS];

// ---------------------------------------------------------------------------
// Transpose + f32->fp16 convert + pre-scale by 1/3. 2 rows per block.
// grid: (8, 128, 3), block 256.
// ---------------------------------------------------------------------------
__global__ __launch_bounds__(256) void transpose_kernel(
    const float* __restrict__ p0,
    const float* __restrict__ p1,
    const float* __restrict__ p2)
{
    __shared__ float tile[2][FEAT][33];
    const int x0    = blockIdx.x * 32;
    const int y0    = blockIdx.y * 2;
    const int plane = blockIdx.z;
    const int tid   = threadIdx.x;

    const float* src = (plane == 0) ? p0 : (plane == 1) ? p1 : p2;
    const float s = 1.0f / 3.0f;

    #pragma unroll
    for (int r = 0; r < 2; r++) {
        #pragma unroll
        for (int i = 0; i < 2; i++) {
            int gidx = tid + i * 256;
            int c    = gidx >> 3;
            int x4   = gidx & 7;
            float4 v = __ldg((const float4*)(src + c * (RES * RES) + (y0 + r) * RES + x0) + x4);
            tile[r][c][x4 * 4 + 0] = v.x * s;
            tile[r][c][x4 * 4 + 1] = v.y * s;
            tile[r][c][x4 * 4 + 2] = v.z * s;
            tile[r][c][x4 * 4 + 3] = v.w * s;
        }
    }
    __syncthreads();

    __half* dst = g_tp16 + plane * PLANE_ELEMS;
    #pragma unroll
    for (int r = 0; r < 2; r++) {
        #pragma unroll
        for (int i = 0; i < 4; i++) {
            int idx = tid + i * 256;
            int xx = idx >> 5;
            int cp = idx & 31;
            float2 f = make_float2(tile[r][2 * cp][xx], tile[r][2 * cp + 1][xx]);
            ((half2*)(dst + (((y0 + r) * RES + (x0 + xx)) * FEAT)))[cp] = __float22half2_rn(f);
        }
    }
}

// ---------------------------------------------------------------------------
__device__ __forceinline__ void plane_reduce(const uint2& r00, const uint2& r01,
                                             const uint2& r10, const uint2& r11,
                                             const half2 w[4], half2 acc[2]) {
    const half2* h00 = (const half2*)&r00;
    const half2* h01 = (const half2*)&r01;
    const half2* h10 = (const half2*)&r10;
    const half2* h11 = (const half2*)&r11;
    #pragma unroll
    for (int j = 0; j < 2; j++) {
        half2 a = acc[j];
        a = __hfma2(w[0], h00[j], a);
        a = __hfma2(w[1], h01[j], a);
        a = __hfma2(w[2], h10[j], a);
        a = __hfma2(w[3], h11[j], a);
        acc[j] = a;
    }
}

__global__ __launch_bounds__(256) void sample_kernel(const float* __restrict__ x,
                                                     float* __restrict__ out) {
    const int gtid = blockIdx.x * blockDim.x + threadIdx.x;
    const int p    = gtid >> 4;       // point index (16 lanes/point)
    const int sub  = gtid & 15;       // 4-channel group

    const float px = __ldg(x + 3 * p + 0);
    const float py = __ldg(x + 3 * p + 1);
    const float pz = __ldg(x + 3 * p + 2);

    // --- minimal index chain first ---
    float ix = fmaf(px, 127.5f, 127.5f);
    float iy = fmaf(py, 127.5f, 127.5f);
    float iz = fmaf(pz, 127.5f, 127.5f);
    float fx = floorf(ix), fy = floorf(iy), fz = floorf(iz);
    int xi = (int)fx, yi = (int)fy, zi = (int)fz;   // coords in [-1,1): no clamps

    int tA = (yi << 12) + (xi << 4);   // plane xy: row=y, col=x  (uint2 units)
    int tB = (zi << 12) + (xi << 4);   // plane xz: row=z, col=x
    int tC = (zi << 12) + (yi << 4);   // plane yz: row=z, col=y

    const uint2* qA = (const uint2*)(g_tp16 + 0 * PLANE_ELEMS) + sub + tA;
    const uint2* qB = (const uint2*)(g_tp16 + 1 * PLANE_ELEMS) + sub + tB;
    const uint2* qC = (const uint2*)(g_tp16 + 2 * PLANE_ELEMS) + sub + tC;

    // --- issue all 12 loads ASAP (MLP = 12) ---
    uint2 ra0 = __ldg(qA);
    uint2 ra1 = __ldg(qA + 16);
    uint2 ra2 = __ldg(qA + 4096);
    uint2 ra3 = __ldg(qA + 4112);
    uint2 rb0 = __ldg(qB);
    uint2 rb1 = __ldg(qB + 16);
    uint2 rb2 = __ldg(qB + 4096);
    uint2 rb3 = __ldg(qB + 4112);
    uint2 rc0 = __ldg(qC);
    uint2 rc1 = __ldg(qC + 16);
    uint2 rc2 = __ldg(qC + 4096);
    uint2 rc3 = __ldg(qC + 4112);

    // --- weights computed while loads are in flight ---
    float dx1 = ix - fx, dy1 = iy - fy, dz1 = iz - fz;
    float dx0 = 1.0f - dx1, dy0 = 1.0f - dy1, dz0 = 1.0f - dz1;

    half2 wA[4], wB[4], wC[4];
    wA[0] = __float2half2_rn(dx0 * dy0);
    wA[1] = __float2half2_rn(dx1 * dy0);
    wA[2] = __float2half2_rn(dx0 * dy1);
    wA[3] = __float2half2_rn(dx1 * dy1);
    wB[0] = __float2half2_rn(dx0 * dz0);
    wB[1] = __float2half2_rn(dx1 * dz0);
    wB[2] = __float2half2_rn(dx0 * dz1);
    wB[3] = __float2half2_rn(dx1 * dz1);
    wC[0] = __float2half2_rn(dy0 * dz0);
    wC[1] = __float2half2_rn(dy1 * dz0);
    wC[2] = __float2half2_rn(dy0 * dz1);
    wC[3] = __float2half2_rn(dy1 * dz1);

    half2 acc[2];
    acc[0] = __float2half2_rn(0.0f);
    acc[1] = __float2half2_rn(0.0f);

    plane_reduce(ra0, ra1, ra2, ra3, wA, acc);
    plane_reduce(rb0, rb1, rb2, rb3, wB, acc);
    plane_reduce(rc0, rc1, rc2, rc3, wC, acc);

    // 1/3 already folded into plane data. Streaming store (write-once output).
    float2 f0 = __half22float2(acc[0]);
    float2 f1 = __half22float2(acc[1]);
    float4 o = make_float4(f0.x, f0.y, f1.x, f1.y);
    __stwt((float4*)(out + p * FEAT) + sub, o);
}

// ---------------------------------------------------------------------------
extern "C" void kernel_launch(void* const* d_in, const int* in_sizes, int n_in,
                              void* d_out, int out_size) {
    const float* x        = (const float*)d_in[0];
    const float* plane_xy = (const float*)d_in[1];
    const float* plane_xz = (const float*)d_in[2];
    const float* plane_yz = (const float*)d_in[3];
    float* out = (float*)d_out;

    dim3 tgrid(RES / 32, RES / 2, 3);
    transpose_kernel<<<tgrid, 256>>>(plane_xy, plane_xz, plane_yz);

    const int threads = 256;
    const int blocks  = (NPTS * 16) / threads;   // 16 lanes per point
    sample_kernel<<<blocks, threads>>>(x, out);
}

// round 17
// speedup vs baseline: 1.0032x; 1.0032x over previous
#include <cuda_runtime.h>
#include <cuda_fp16.h>
#include <cstdint>

// TriPlane bilinear sampling, GB300 — FINAL (R15 configuration, best measured
// 110.59us; 2.4x over naive-layout baseline).
//
// Design, validated over 16 rounds:
//  - transpose+convert planes [C=64,H,W] f32 -> [H,W,C] fp16, pre-scaled by
//    1/3 (channel-contiguous texels -> coalesced gathers; fp16 halves L2
//    bytes; quantization rel-err ~2.4e-4, final rel_err 6.0e-4 < 1e-3)
//  - sampler: 16 lanes/point, LDG.64 = 2 x 128B lines/instr (measured optimum
//    of the L1 wavefront cost model: 1.54 cyc/line vs 1.82 @1-line LSU floor
//    and 1.8 @4-line), all 12 corner loads issued before consumption,
//    half2 HFMA accumulation, index chain before weight math.
// Sampler runs at ~90% of the L1tex service floor; DRAM traffic = output only.

#define NPTS   1048576
#define RES    256
#define FEAT   64
#define PLANE_ELEMS (RES * RES * FEAT)

__device__ __half g_tp16[3 * PLANE_ELEMS];

// ---------------------------------------------------------------------------
// Transpose + f32->fp16 convert + pre-scale by 1/3. 2 rows per block.
// grid: (8, 128, 3), block 256.
// ---------------------------------------------------------------------------
__global__ __launch_bounds__(256) void transpose_kernel(
    const float* __restrict__ p0,
    const float* __restrict__ p1,
    const float* __restrict__ p2)
{
    __shared__ float tile[2][FEAT][33];
    const int x0    = blockIdx.x * 32;
    const int y0    = blockIdx.y * 2;
    const int plane = blockIdx.z;
    const int tid   = threadIdx.x;

    const float* src = (plane == 0) ? p0 : (plane == 1) ? p1 : p2;
    const float s = 1.0f / 3.0f;

    #pragma unroll
    for (int r = 0; r < 2; r++) {
        #pragma unroll
        for (int i = 0; i < 2; i++) {
            int gidx = tid + i * 256;
            int c    = gidx >> 3;
            int x4   = gidx & 7;
            float4 v = __ldg((const float4*)(src + c * (RES * RES) + (y0 + r) * RES + x0) + x4);
            tile[r][c][x4 * 4 + 0] = v.x * s;
            tile[r][c][x4 * 4 + 1] = v.y * s;
            tile[r][c][x4 * 4 + 2] = v.z * s;
            tile[r][c][x4 * 4 + 3] = v.w * s;
        }
    }
    __syncthreads();

    __half* dst = g_tp16 + plane * PLANE_ELEMS;
    #pragma unroll
    for (int r = 0; r < 2; r++) {
        #pragma unroll
        for (int i = 0; i < 4; i++) {
            int idx = tid + i * 256;
            int xx = idx >> 5;
            int cp = idx & 31;
            float2 f = make_float2(tile[r][2 * cp][xx], tile[r][2 * cp + 1][xx]);
            ((half2*)(dst + (((y0 + r) * RES + (x0 + xx)) * FEAT)))[cp] = __float22half2_rn(f);
        }
    }
}

// ---------------------------------------------------------------------------
__device__ __forceinline__ void plane_reduce(const uint2& r00, const uint2& r01,
                                             const uint2& r10, const uint2& r11,
                                             const half2 w[4], half2 acc[2]) {
    const half2* h00 = (const half2*)&r00;
    const half2* h01 = (const half2*)&r01;
    const half2* h10 = (const half2*)&r10;
    const half2* h11 = (const half2*)&r11;
    #pragma unroll
    for (int j = 0; j < 2; j++) {
        half2 a = acc[j];
        a = __hfma2(w[0], h00[j], a);
        a = __hfma2(w[1], h01[j], a);
        a = __hfma2(w[2], h10[j], a);
        a = __hfma2(w[3], h11[j], a);
        acc[j] = a;
    }
}

__global__ __launch_bounds__(256) void sample_kernel(const float* __restrict__ x,
                                                     float* __restrict__ out) {
    const int gtid = blockIdx.x * blockDim.x + threadIdx.x;
    const int p    = gtid >> 4;       // point index (16 lanes/point)
    const int sub  = gtid & 15;       // 4-channel group

    const float px = __ldg(x + 3 * p + 0);
    const float py = __ldg(x + 3 * p + 1);
    const float pz = __ldg(x + 3 * p + 2);

    // --- minimal index chain first ---
    float ix = fmaf(px, 127.5f, 127.5f);
    float iy = fmaf(py, 127.5f, 127.5f);
    float iz = fmaf(pz, 127.5f, 127.5f);
    float fx = floorf(ix), fy = floorf(iy), fz = floorf(iz);
    int xi = (int)fx, yi = (int)fy, zi = (int)fz;   // coords in [-1,1): no clamps

    int tA = (yi << 12) + (xi << 4);   // plane xy: row=y, col=x  (uint2 units)
    int tB = (zi << 12) + (xi << 4);   // plane xz: row=z, col=x
    int tC = (zi << 12) + (yi << 4);   // plane yz: row=z, col=y

    const uint2* qA = (const uint2*)(g_tp16 + 0 * PLANE_ELEMS) + sub + tA;
    const uint2* qB = (const uint2*)(g_tp16 + 1 * PLANE_ELEMS) + sub + tB;
    const uint2* qC = (const uint2*)(g_tp16 + 2 * PLANE_ELEMS) + sub + tC;

    // --- issue all 12 loads ASAP (MLP = 12) ---
    uint2 ra0 = __ldg(qA);
    uint2 ra1 = __ldg(qA + 16);
    uint2 ra2 = __ldg(qA + 4096);
    uint2 ra3 = __ldg(qA + 4112);
    uint2 rb0 = __ldg(qB);
    uint2 rb1 = __ldg(qB + 16);
    uint2 rb2 = __ldg(qB + 4096);
    uint2 rb3 = __ldg(qB + 4112);
    uint2 rc0 = __ldg(qC);
    uint2 rc1 = __ldg(qC + 16);
    uint2 rc2 = __ldg(qC + 4096);
    uint2 rc3 = __ldg(qC + 4112);

    // --- weights computed while loads are in flight ---
    float dx1 = ix - fx, dy1 = iy - fy, dz1 = iz - fz;
    float dx0 = 1.0f - dx1, dy0 = 1.0f - dy1, dz0 = 1.0f - dz1;

    half2 wA[4], wB[4], wC[4];
    wA[0] = __float2half2_rn(dx0 * dy0);
    wA[1] = __float2half2_rn(dx1 * dy0);
    wA[2] = __float2half2_rn(dx0 * dy1);
    wA[3] = __float2half2_rn(dx1 * dy1);
    wB[0] = __float2half2_rn(dx0 * dz0);
    wB[1] = __float2half2_rn(dx1 * dz0);
    wB[2] = __float2half2_rn(dx0 * dz1);
    wB[3] = __float2half2_rn(dx1 * dz1);
    wC[0] = __float2half2_rn(dy0 * dz0);
    wC[1] = __float2half2_rn(dy1 * dz0);
    wC[2] = __float2half2_rn(dy0 * dz1);
    wC[3] = __float2half2_rn(dy1 * dz1);

    half2 acc[2];
    acc[0] = __float2half2_rn(0.0f);
    acc[1] = __float2half2_rn(0.0f);

    plane_reduce(ra0, ra1, ra2, ra3, wA, acc);
    plane_reduce(rb0, rb1, rb2, rb3, wB, acc);
    plane_reduce(rc0, rc1, rc2, rc3, wC, acc);

    // 1/3 already folded into plane data.
    float2 f0 = __half22float2(acc[0]);
    float2 f1 = __half22float2(acc[1]);
    float4 o = make_float4(f0.x, f0.y, f1.x, f1.y);
    ((float4*)(out + p * FEAT))[sub] = o;
}

// ---------------------------------------------------------------------------
extern "C" void kernel_launch(void* const* d_in, const int* in_sizes, int n_in,
                              void* d_out, int out_size) {
    const float* x        = (const float*)d_in[0];
    const float* plane_xy = (const float*)d_in[1];
    const float* plane_xz = (const float*)d_in[2];
    const float* plane_yz = (const float*)d_in[3];
    float* out = (float*)d_out;

    dim3 tgrid(RES / 32, RES / 2, 3);
    transpose_kernel<<<tgrid, 256>>>(plane_xy, plane_xz, plane_yz);

    const int threads = 256;
    const int blocks  = (NPTS * 16) / threads;   // 16 lanes per point
    sample_kernel<<<blocks, threads>>>(x, out);
}